// round 12
// baseline (speedup 1.0000x reference)
#include <cuda_runtime.h>
#include <math.h>

typedef unsigned long long u64;

#define BL    800
#define NIT   8192
#define NROW  8992

#define OFF_CATGY 0
#define OFF_DSC   128000
#define OFF_DCAND 134400
#define OFF_EMB   1182976
#define OFF_ECAND 1285376
#define OFF_LOSS  2333952

__device__ float g_wf  [128 * 128];
__device__ float g_bf  [128];
__device__ float g_agg [128 * 128];
__device__ float g_pd  [128 * 128];
__device__ float g_pdT [128 * 128];
__device__ float g_pk  [BL * 128];
__device__ float g_pkc [NIT * 128];

union F4U { float4 f; u64 u[2]; float s[4]; };

__device__ __forceinline__ u64 pack2(float lo, float hi) {
    u64 r; asm("mov.b64 %0, {%1,%2};" : "=l"(r) : "f"(lo), "f"(hi)); return r;
}
__device__ __forceinline__ void unpack2(u64 v, float& lo, float& hi) {
    asm("mov.b64 {%0,%1}, %2;" : "=f"(lo), "=f"(hi) : "l"(v));
}
__device__ __forceinline__ u64 fma2(u64 a, u64 b, u64 c) {
    u64 r; asm("fma.rn.f32x2 %0, %1, %2, %3;" : "=l"(r) : "l"(a), "l"(b), "l"(c)); return r;
}
__device__ __forceinline__ u64 add2(u64 a, u64 b) {
    u64 r; asm("add.rn.f32x2 %0, %1, %2;" : "=l"(r) : "l"(a), "l"(b)); return r;
}
__device__ __forceinline__ u64 relu2(u64 v) {
    float a, b; unpack2(v, a, b);
    a = fmaxf(a, 0.f); b = fmaxf(b, 0.f);
    return pack2(a, b);
}

#define MICRO44(AS, BS)                                                       \
    u64 acc[4][2];                                                            \
    _Pragma("unroll")                                                         \
    for (int i = 0; i < 4; i++) { acc[i][0] = 0ull; acc[i][1] = 0ull; }       \
    _Pragma("unroll 4")                                                       \
    for (int k = 0; k < 128; k++) {                                           \
        F4U a4; a4.f = *(const float4*)&(AS)[k * 68 + ty * 4];                \
        F4U q;  q.f  = *(const float4*)&(BS)[k * 68 + tx * 4];                \
        _Pragma("unroll")                                                     \
        for (int i = 0; i < 4; i++) {                                         \
            u64 ad = pack2(a4.s[i], a4.s[i]);                                 \
            acc[i][0] = fma2(ad, q.u[0], acc[i][0]);                          \
            acc[i][1] = fma2(ad, q.u[1], acc[i][1]);                          \
        }                                                                     \
    }

// ===========================================================================
// kLSE: 256 blocks, fused emb@Wd + logsumexp (64 l x 64 cols per block)
// ===========================================================================
__global__ void __launch_bounds__(256, 3)
kLSE(const int* __restrict__ inp, const float* __restrict__ table,
     const float* __restrict__ Wd, float* __restrict__ agg) {
    __shared__ __align__(16) char sb[69632];
    float* As = (float*)sb;
    float* Bs = (float*)(sb + 34816);
    float* red = As;
    int bx = blockIdx.x, tid = threadIdx.x;
    int tx = tid & 15, ty = tid >> 4;
    int b = bx >> 4, cb = bx & 15;
    const float4* t4 = (const float4*)table;

#pragma unroll
    for (int p = 0; p < 8; p++) {
        int i = tid + p * 256;
        int l = i & 63, k4 = i >> 6;
        float4 v = make_float4(0.f, 0.f, 0.f, 0.f);
        if (l < 50) { int idx = inp[b * 50 + l]; v = t4[idx * 32 + k4]; }
        As[(k4 * 4 + 0) * 68 + l] = v.x;
        As[(k4 * 4 + 1) * 68 + l] = v.y;
        As[(k4 * 4 + 2) * 68 + l] = v.z;
        As[(k4 * 4 + 3) * 68 + l] = v.w;
    }
#pragma unroll
    for (int p = 0; p < 8; p++) {
        int i = tid + p * 256;
        int k = i >> 4, c4 = (i & 15) * 4;
        *(float4*)&Bs[k * 68 + c4] = *(const float4*)(Wd + k * 1024 + cb * 64 + c4);
    }
    __syncthreads();

    MICRO44(As, Bs);

    float vals[4][4];
#pragma unroll
    for (int i = 0; i < 4; i++) {
        unpack2(acc[i][0], vals[i][0], vals[i][1]);
        unpack2(acc[i][1], vals[i][2], vals[i][3]);
    }
    int nval = 50 - ty * 4; if (nval > 4) nval = 4; if (nval < 0) nval = 0;

    __syncthreads();
#pragma unroll
    for (int u = 0; u < 4; u++) {
        float mm = -INFINITY;
        for (int i = 0; i < nval; i++) mm = fmaxf(mm, vals[i][u]);
        red[ty * 68 + tx * 4 + u] = mm;
    }
    __syncthreads();
    float M[4];
#pragma unroll
    for (int u = 0; u < 4; u++) {
        float mm = -INFINITY;
#pragma unroll
        for (int t = 0; t < 16; t++) mm = fmaxf(mm, red[t * 68 + tx * 4 + u]);
        M[u] = mm;
    }
    __syncthreads();
#pragma unroll
    for (int u = 0; u < 4; u++) {
        float s = 0.f;
        for (int i = 0; i < nval; i++) s += __expf(vals[i][u] - M[u]);
        red[ty * 68 + tx * 4 + u] = s;
    }
    __syncthreads();
    if (ty == 0) {
#pragma unroll
        for (int u = 0; u < 4; u++) {
            float S = 0.f;
#pragma unroll
            for (int t = 0; t < 16; t++) S += red[t * 68 + tx * 4 + u];
            agg[b * 1024 + cb * 64 + tx * 4 + u] = M[u] + __logf(S);
        }
    }
}

// ===========================================================================
// kFold: blocks 0..3 wf tiles (64x64); block 4 bf
// ===========================================================================
__global__ void __launch_bounds__(256, 3)
kFold(const float* __restrict__ Wk, const float* __restrict__ Wk1,
      const float* __restrict__ bk,
      float* __restrict__ wf, float* __restrict__ bf) {
    __shared__ __align__(16) char sb[69632];
    float* As = (float*)sb;
    float* Bs = (float*)(sb + 34816);
    int bx = blockIdx.x, tid = threadIdx.x;
    int tx = tid & 15, ty = tid >> 4;

    if (bx < 4) {
        int bm = (bx >> 1) * 64, bn = (bx & 1) * 64;
#pragma unroll
        for (int p = 0; p < 8; p++) {
            int i = tid + p * 256;
            int r = i & 63, k4 = i >> 6;
            float4 v = *(const float4*)(Wk + (bm + r) * 128 + k4 * 4);
            As[(k4 * 4 + 0) * 68 + r] = v.x;
            As[(k4 * 4 + 1) * 68 + r] = v.y;
            As[(k4 * 4 + 2) * 68 + r] = v.z;
            As[(k4 * 4 + 3) * 68 + r] = v.w;
        }
#pragma unroll
        for (int p = 0; p < 8; p++) {
            int i = tid + p * 256;
            int k = i >> 4, c4 = (i & 15) * 4;
            *(float4*)&Bs[k * 68 + c4] = *(const float4*)(Wk1 + k * 128 + bn + c4);
        }
        __syncthreads();

        MICRO44(As, Bs);

#pragma unroll
        for (int i = 0; i < 4; i++) {
            F4U o; o.u[0] = acc[i][0]; o.u[1] = acc[i][1];
            *(float4*)(wf + (bm + ty * 4 + i) * 128 + bn + tx * 4) = o.f;
        }
    } else {
        if (tid < 128) {
            float acc = 0.f;
#pragma unroll 8
            for (int h = 0; h < 128; h++)
                acc = fmaf(__ldg(bk + h), __ldg(Wk1 + h * 128 + tid), acc);
            bf[tid] = acc;
        }
    }
}

// ===========================================================================
// kPkGemm: 282 blocks, pk/pkc GEMM (64 rows x 64 cols) + gather + emb out
// ===========================================================================
__global__ void __launch_bounds__(256, 3)
kPkGemm(const int* __restrict__ inp, const int* __restrict__ cand,
        const float* __restrict__ table,
        const float* __restrict__ wf, const float* __restrict__ bf,
        float* __restrict__ out,
        float* __restrict__ pk, float* __restrict__ pkc) {
    __shared__ __align__(16) char sb[69632];
    float* As = (float*)sb;
    float* Bs = (float*)(sb + 34816);
    int bx = blockIdx.x, tid = threadIdx.x;
    int tx = tid & 15, ty = tid >> 4;

    int rb = bx >> 1, cs = bx & 1;
    int bm = rb * 64, bn = cs * 64;
    const float4* t4 = (const float4*)table;
#pragma unroll
    for (int p = 0; p < 8; p++) {
        int i = tid + p * 256;
        int r = i & 63, k4 = i >> 6;
        int row = bm + r;
        float4 v = make_float4(0.f, 0.f, 0.f, 0.f);
        if (row < NROW) {
            int idx = (row < BL) ? inp[row] : cand[row - BL];
            v = t4[idx * 32 + k4];
            if (cs == 0) {
                float* dst = (row < BL) ? (out + OFF_EMB + row * 128)
                                        : (out + OFF_ECAND + (row - BL) * 128);
                ((float4*)dst)[k4] = v;
            }
        }
        As[(k4 * 4 + 0) * 68 + r] = v.x;
        As[(k4 * 4 + 1) * 68 + r] = v.y;
        As[(k4 * 4 + 2) * 68 + r] = v.z;
        As[(k4 * 4 + 3) * 68 + r] = v.w;
    }
#pragma unroll
    for (int p = 0; p < 8; p++) {
        int i = tid + p * 256;
        int k = i >> 4, c4 = (i & 15) * 4;
        *(float4*)&Bs[k * 68 + c4] = *(const float4*)(wf + k * 128 + bn + c4);
    }
    __syncthreads();

    MICRO44(As, Bs);

    float4 bv = *(const float4*)(bf + bn + tx * 4);
#pragma unroll
    for (int i = 0; i < 4; i++) {
        int row = bm + ty * 4 + i;
        if (row >= NROW) continue;
        F4U o; o.u[0] = acc[i][0]; o.u[1] = acc[i][1];
        o.s[0] += bv.x; o.s[1] += bv.y; o.s[2] += bv.z; o.s[3] += bv.w;
        float* dst = (row < BL) ? (pk + row * 128) : (pkc + (row - BL) * 128);
        *(float4*)(dst + bn + tx * 4) = o.f;
    }
}

// ===========================================================================
// kHeads: blocks 0..31 catgy; 32..35 pd(+pdT); 36 loss
// ===========================================================================
__global__ void __launch_bounds__(256, 3)
kHeads(const float* __restrict__ agg,
       const float* __restrict__ Wc, const float* __restrict__ bc,
       const float* __restrict__ W1, const float* __restrict__ b1,
       float* __restrict__ out,
       float* __restrict__ pd, float* __restrict__ pdT) {
    __shared__ __align__(16) char sb[69632];
    float* As = (float*)sb;
    float* Bs = (float*)(sb + 34816);
    int bx = blockIdx.x, tid = threadIdx.x;
    int tx = tid & 15, ty = tid >> 4;

    if (bx < 36) {
        const float* B; const float* bias; float* C; float* CT; int N, bm, bn;
        if (bx < 32) { B = Wc; bias = bc; C = out + OFF_CATGY; CT = nullptr;
                       N = 1000; bm = (bx >> 4) * 64; bn = (bx & 15) * 64; }
        else         { int t = bx - 32; B = W1; bias = b1; C = pd; CT = pdT;
                       N = 128; bm = (t >> 1) * 64; bn = (t & 1) * 64; }

#pragma unroll
        for (int p = 0; p < 8; p++) {
            int i = tid + p * 256;
            int r = i & 63, k4 = i >> 6;
            float4 v = *(const float4*)(agg + (bm + r) * 128 + k4 * 4);
            As[(k4 * 4 + 0) * 68 + r] = v.x;
            As[(k4 * 4 + 1) * 68 + r] = v.y;
            As[(k4 * 4 + 2) * 68 + r] = v.z;
            As[(k4 * 4 + 3) * 68 + r] = v.w;
        }
#pragma unroll
        for (int p = 0; p < 8; p++) {
            int i = tid + p * 256;
            int k = i >> 4, c4 = (i & 15) * 4;
            int c = bn + c4;
            float4 v = make_float4(0.f, 0.f, 0.f, 0.f);
            const float* brow = B + k * N;
            if (c + 3 < N) v = *(const float4*)(brow + c);
            else {
                if (c     < N) v.x = brow[c];
                if (c + 1 < N) v.y = brow[c + 1];
                if (c + 2 < N) v.z = brow[c + 2];
            }
            *(float4*)&Bs[k * 68 + c4] = v;
        }
        __syncthreads();

        MICRO44(As, Bs);

        int c0 = bn + tx * 4;
        float bv[4];
#pragma unroll
        for (int u = 0; u < 4; u++) bv[u] = (c0 + u < N) ? bias[c0 + u] : 0.f;
#pragma unroll
        for (int i = 0; i < 4; i++) {
            int r = bm + ty * 4 + i;
            F4U o; o.u[0] = acc[i][0]; o.u[1] = acc[i][1];
            o.s[0] += bv[0]; o.s[1] += bv[1]; o.s[2] += bv[2]; o.s[3] += bv[3];
            if (c0 + 3 < N) *(float4*)(C + r * N + c0) = o.f;
            else {
#pragma unroll
                for (int u = 0; u < 4; u++)
                    if (c0 + u < N) C[r * N + c0 + u] = o.s[u];
            }
            if (CT) {
#pragma unroll
                for (int u = 0; u < 4; u++) CT[(c0 + u) * 128 + r] = o.s[u];
            }
        }
    } else {
        float* inv  = (float*)sb;
        float* redl = (float*)sb + 128;
        if (tid < 128) {
            const float* a = agg + tid * 128;
            float s = 0.f;
#pragma unroll 8
            for (int h = 0; h < 128; h++) s = fmaf(a[h], a[h], s);
            inv[tid] = 1.f / (sqrtf(s) + 1e-12f);
        }
        __syncthreads();
        if (tid < 128) {
            float accv = 0.f;
            for (int b = 0; b < 16; b++) {
                float sv = 0.f, sq = 0.f;
#pragma unroll
                for (int d = 0; d < 8; d++) {
                    float x = agg[(b * 8 + d) * 128 + tid] * inv[b * 8 + d];
                    sv += x; sq = fmaf(x, x, sq);
                }
                accv += sv * sv - sq;
            }
            redl[tid] = accv;
        }
        __syncthreads();
        if (tid == 0) {
            float t = 0.f;
            for (int i = 0; i < 128; i++) t += redl[i];
            out[OFF_LOSS] = t / 896.f;
        }
    }
}

// ===========================================================================
// kScores: blocks 0..255 cand relu-GEMM (64x64); 256..275 dscore
// ===========================================================================
__global__ void __launch_bounds__(256, 3)
kScores(const float* __restrict__ pdT, const float* __restrict__ pd,
        const float* __restrict__ pkc, const float* __restrict__ pk,
        const float* __restrict__ w,
        float* __restrict__ out) {
    __shared__ __align__(16) char sb[70656];
    int bx = blockIdx.x, tid = threadIdx.x;

    if (bx < 256) {
        float* Ps  = (float*)sb;
        float* Qs  = (float*)(sb + 34816);
        u64*   ws2 = (u64*)(sb + 69632);
        int bdb = (bx >> 7) * 64, itb = (bx & 127) * 64;
        int tx = tid & 15, ty = tid >> 4;

#pragma unroll
        for (int p = 0; p < 8; p++) {
            int i = tid + p * 256;
            int k = i >> 4, r4 = (i & 15) * 4;
            *(float4*)&Ps[k * 68 + r4] = *(const float4*)(pdT + k * 128 + bdb + r4);
        }
#pragma unroll
        for (int p = 0; p < 8; p++) {
            int i = tid + p * 256;
            int itl = i & 63, k4 = i >> 6;
            float4 v = *(const float4*)(pkc + (itb + itl) * 128 + k4 * 4);
            Qs[(k4 * 4 + 0) * 68 + itl] = v.x;
            Qs[(k4 * 4 + 1) * 68 + itl] = v.y;
            Qs[(k4 * 4 + 2) * 68 + itl] = v.z;
            Qs[(k4 * 4 + 3) * 68 + itl] = v.w;
        }
        if (tid < 128) { float wv = w[tid]; ws2[tid] = pack2(wv, wv); }
        __syncthreads();

        u64 acc[4][2];
#pragma unroll
        for (int i = 0; i < 4; i++) { acc[i][0] = 0ull; acc[i][1] = 0ull; }

#pragma unroll 4
        for (int k = 0; k < 128; k++) {
            F4U a4; a4.f = *(const float4*)&Ps[k * 68 + ty * 4];
            F4U q;  q.f  = *(const float4*)&Qs[k * 68 + tx * 4];
            u64 w2 = ws2[k];
#pragma unroll
            for (int i = 0; i < 4; i++) {
                u64 ad = pack2(a4.s[i], a4.s[i]);
                acc[i][0] = fma2(relu2(add2(ad, q.u[0])), w2, acc[i][0]);
                acc[i][1] = fma2(relu2(add2(ad, q.u[1])), w2, acc[i][1]);
            }
        }

#pragma unroll
        for (int i = 0; i < 4; i++) {
            int row = bdb + ty * 4 + i;
            F4U o; o.u[0] = acc[i][0]; o.u[1] = acc[i][1];
            *(float4*)(out + OFF_DCAND + (size_t)row * NIT + itb + tx * 4) = o.f;
        }
    } else {
        int wid0 = (bx - 256) * 8 + (tid >> 5);
        int lane = tid & 31;
        const float4* w4 = (const float4*)w;
        float4 ww = w4[lane];
#pragma unroll
        for (int rep = 0; rep < 5; rep++) {
            int wid = wid0 + rep * 160;
            if (wid >= 800) break;
            int b = wid / 50, l = wid % 50;
            const float4* k4 = (const float4*)(pk + (b * 50 + l) * 128);
            float4 c = k4[lane];
#pragma unroll
            for (int d = 0; d < 8; d++) {
                const float4* p4 = (const float4*)(pd + (b * 8 + d) * 128);
                float4 a = p4[lane];
                float acc = fmaxf(a.x + c.x, 0.f) * ww.x
                          + fmaxf(a.y + c.y, 0.f) * ww.y
                          + fmaxf(a.z + c.z, 0.f) * ww.z
                          + fmaxf(a.w + c.w, 0.f) * ww.w;
#pragma unroll
                for (int o = 16; o > 0; o >>= 1) acc += __shfl_down_sync(0xffffffffu, acc, o);
                if (lane == 0) out[OFF_DSC + b * 400 + l * 8 + d] = acc;
            }
        }
    }
}

// ===========================================================================
extern "C" void kernel_launch(void* const* d_in, const int* in_sizes, int n_in,
                              void* d_out, int out_size) {
    const int*   input = (const int*)d_in[0];
    const int*   cand  = (const int*)d_in[1];
    const float* table = (const float*)d_in[4];
    const float* Wd    = (const float*)d_in[5];
    const float* Wk    = (const float*)d_in[6];
    const float* bk    = (const float*)d_in[7];
    const float* W1    = (const float*)d_in[8];
    const float* b1    = (const float*)d_in[9];
    const float* wsc   = (const float*)d_in[10];
    const float* Wc    = (const float*)d_in[11];
    const float* bc    = (const float*)d_in[12];
    float* out = (float*)d_out;

    float *wf, *bf, *agg, *pd, *pdT, *pk, *pkc;
    cudaGetSymbolAddress((void**)&wf,  g_wf);
    cudaGetSymbolAddress((void**)&bf,  g_bf);
    cudaGetSymbolAddress((void**)&agg, g_agg);
    cudaGetSymbolAddress((void**)&pd,  g_pd);
    cudaGetSymbolAddress((void**)&pdT, g_pdT);
    cudaGetSymbolAddress((void**)&pk,  g_pk);
    cudaGetSymbolAddress((void**)&pkc, g_pkc);

    const float* Wk1 = W1 + 128 * 128;

    // One-time host-side stream/event setup (no device memory involved).
    static cudaStream_t s2 = nullptr;
    static cudaEvent_t  eFork = nullptr, eP = nullptr;
    if (s2 == nullptr) {
        cudaStreamCreateWithFlags(&s2, cudaStreamNonBlocking);
        cudaEventCreateWithFlags(&eFork, cudaEventDisableTiming);
        cudaEventCreateWithFlags(&eP,    cudaEventDisableTiming);
    }

    // Fork: s2 branches off the launch stream.
    cudaEventRecord(eFork, 0);
    cudaStreamWaitEvent(s2, eFork, 0);

    // Branch A (launch stream): LSE -> heads
    kLSE<<<256, 256>>>(input, table, Wd, agg);

    // Branch B (s2): fold -> pk/pkc GEMM
    kFold<<<5, 256, 0, s2>>>(Wk, Wk1, bk, wf, bf);
    kPkGemm<<<282, 256, 0, s2>>>(input, cand, table, wf, bf, out, pk, pkc);
    cudaEventRecord(eP, s2);

    // Heads depends only on agg (in-order after kLSE on launch stream).
    kHeads<<<37, 256>>>(agg, Wc, bc, W1, b1, out, pd, pdT);

    // Join: scores need pkc/pk (branch B) + pd/pdT (branch A).
    cudaStreamWaitEvent(0, eP, 0);
    kScores<<<276, 256>>>(pdT, pd, pkc, pk, wsc, out);
}

// round 13
// speedup vs baseline: 1.2163x; 1.2163x over previous
#include <cuda_runtime.h>
#include <math.h>

typedef unsigned long long u64;

#define BL    800
#define NIT   8192
#define NROW  8992

#define OFF_CATGY 0
#define OFF_DSC   128000
#define OFF_DCAND 134400
#define OFF_EMB   1182976
#define OFF_ECAND 1285376
#define OFF_LOSS  2333952

__device__ float g_wf  [128 * 128];
__device__ float g_bf  [128];
__device__ float g_agg [128 * 128];
__device__ float g_pd  [128 * 128];
__device__ float g_pdT [128 * 128];
__device__ float g_tpk [1024 * 128];   // (table @ wf) + bf, padded rows

union F4U { float4 f; u64 u[2]; float s[4]; };

__device__ __forceinline__ u64 pack2(float lo, float hi) {
    u64 r; asm("mov.b64 %0, {%1,%2};" : "=l"(r) : "f"(lo), "f"(hi)); return r;
}
__device__ __forceinline__ void unpack2(u64 v, float& lo, float& hi) {
    asm("mov.b64 {%0,%1}, %2;" : "=f"(lo), "=f"(hi) : "l"(v));
}
__device__ __forceinline__ u64 fma2(u64 a, u64 b, u64 c) {
    u64 r; asm("fma.rn.f32x2 %0, %1, %2, %3;" : "=l"(r) : "l"(a), "l"(b), "l"(c)); return r;
}
__device__ __forceinline__ u64 add2(u64 a, u64 b) {
    u64 r; asm("add.rn.f32x2 %0, %1, %2;" : "=l"(r) : "l"(a), "l"(b)); return r;
}
__device__ __forceinline__ u64 relu2(u64 v) {
    float a, b; unpack2(v, a, b);
    a = fmaxf(a, 0.f); b = fmaxf(b, 0.f);
    return pack2(a, b);
}

#define MICRO44(AS, BS)                                                       \
    u64 acc[4][2];                                                            \
    _Pragma("unroll")                                                         \
    for (int i = 0; i < 4; i++) { acc[i][0] = 0ull; acc[i][1] = 0ull; }       \
    _Pragma("unroll 4")                                                       \
    for (int k = 0; k < 128; k++) {                                           \
        F4U a4; a4.f = *(const float4*)&(AS)[k * 68 + ty * 4];                \
        F4U q;  q.f  = *(const float4*)&(BS)[k * 68 + tx * 4];                \
        _Pragma("unroll")                                                     \
        for (int i = 0; i < 4; i++) {                                         \
            u64 ad = pack2(a4.s[i], a4.s[i]);                                 \
            acc[i][0] = fma2(ad, q.u[0], acc[i][0]);                          \
            acc[i][1] = fma2(ad, q.u[1], acc[i][1]);                          \
        }                                                                     \
    }

// ===========================================================================
// K1: blocks 0..255 : fused emb@Wd + logsumexp (64 l x 64 cols per block)
//     blocks 256..259: wf = Wk@Wk1 (64x64 tiles)
//     block  260     : bf = bk@Wk1
// ===========================================================================
__global__ void __launch_bounds__(256, 3)
k1_lse_fold(const int* __restrict__ inp,
            const float* __restrict__ table,
            const float* __restrict__ Wd,
            const float* __restrict__ Wk,
            const float* __restrict__ Wk1,
            const float* __restrict__ bk,
            float* __restrict__ agg,
            float* __restrict__ wf, float* __restrict__ bf) {
    __shared__ __align__(16) char sb[69632];
    float* As = (float*)sb;
    float* Bs = (float*)(sb + 34816);
    float* red = As;
    int bx = blockIdx.x, tid = threadIdx.x;
    int tx = tid & 15, ty = tid >> 4;

    if (bx < 256) {
        int b = bx >> 4, cb = bx & 15;
        const float4* t4 = (const float4*)table;
#pragma unroll
        for (int p = 0; p < 8; p++) {
            int i = tid + p * 256;
            int l = i & 63, k4 = i >> 6;
            float4 v = make_float4(0.f, 0.f, 0.f, 0.f);
            if (l < 50) { int idx = inp[b * 50 + l]; v = t4[idx * 32 + k4]; }
            As[(k4 * 4 + 0) * 68 + l] = v.x;
            As[(k4 * 4 + 1) * 68 + l] = v.y;
            As[(k4 * 4 + 2) * 68 + l] = v.z;
            As[(k4 * 4 + 3) * 68 + l] = v.w;
        }
#pragma unroll
        for (int p = 0; p < 8; p++) {
            int i = tid + p * 256;
            int k = i >> 4, c4 = (i & 15) * 4;
            *(float4*)&Bs[k * 68 + c4] = *(const float4*)(Wd + k * 1024 + cb * 64 + c4);
        }
        __syncthreads();

        MICRO44(As, Bs);

        float vals[4][4];
#pragma unroll
        for (int i = 0; i < 4; i++) {
            unpack2(acc[i][0], vals[i][0], vals[i][1]);
            unpack2(acc[i][1], vals[i][2], vals[i][3]);
        }
        int nval = 50 - ty * 4; if (nval > 4) nval = 4; if (nval < 0) nval = 0;

        __syncthreads();
#pragma unroll
        for (int u = 0; u < 4; u++) {
            float mm = -INFINITY;
            for (int i = 0; i < nval; i++) mm = fmaxf(mm, vals[i][u]);
            red[ty * 68 + tx * 4 + u] = mm;
        }
        __syncthreads();
        float M[4];
#pragma unroll
        for (int u = 0; u < 4; u++) {
            float mm = -INFINITY;
#pragma unroll
            for (int t = 0; t < 16; t++) mm = fmaxf(mm, red[t * 68 + tx * 4 + u]);
            M[u] = mm;
        }
        __syncthreads();
#pragma unroll
        for (int u = 0; u < 4; u++) {
            float s = 0.f;
            for (int i = 0; i < nval; i++) s += __expf(vals[i][u] - M[u]);
            red[ty * 68 + tx * 4 + u] = s;
        }
        __syncthreads();
        if (ty == 0) {
#pragma unroll
            for (int u = 0; u < 4; u++) {
                float S = 0.f;
#pragma unroll
                for (int t = 0; t < 16; t++) S += red[t * 68 + tx * 4 + u];
                agg[b * 1024 + cb * 64 + tx * 4 + u] = M[u] + __logf(S);
            }
        }
    } else if (bx < 260) {
        int t = bx - 256;
        int bm = (t >> 1) * 64, bn = (t & 1) * 64;
#pragma unroll
        for (int p = 0; p < 8; p++) {
            int i = tid + p * 256;
            int r = i & 63, k4 = i >> 6;
            float4 v = *(const float4*)(Wk + (bm + r) * 128 + k4 * 4);
            As[(k4 * 4 + 0) * 68 + r] = v.x;
            As[(k4 * 4 + 1) * 68 + r] = v.y;
            As[(k4 * 4 + 2) * 68 + r] = v.z;
            As[(k4 * 4 + 3) * 68 + r] = v.w;
        }
#pragma unroll
        for (int p = 0; p < 8; p++) {
            int i = tid + p * 256;
            int k = i >> 4, c4 = (i & 15) * 4;
            *(float4*)&Bs[k * 68 + c4] = *(const float4*)(Wk1 + k * 128 + bn + c4);
        }
        __syncthreads();

        MICRO44(As, Bs);

#pragma unroll
        for (int i = 0; i < 4; i++) {
            F4U o; o.u[0] = acc[i][0]; o.u[1] = acc[i][1];
            *(float4*)(wf + (bm + ty * 4 + i) * 128 + bn + tx * 4) = o.f;
        }
    } else {
        if (tid < 128) {
            float acc = 0.f;
#pragma unroll 8
            for (int h = 0; h < 128; h++)
                acc = fmaf(__ldg(bk + h), __ldg(Wk1 + h * 128 + tid), acc);
            bf[tid] = acc;
        }
    }
}

// ===========================================================================
// K2: blocks 0..31: catgy 64x64; 32..35: pd (+pdT); 36: loss;
//     blocks 37..68: tpk = table @ wf + bf  (16 row-blocks x 2 col-halves)
// ===========================================================================
__global__ void __launch_bounds__(256, 3)
k2_heads_tpk(const float* __restrict__ agg,
             const float* __restrict__ Wc, const float* __restrict__ bc,
             const float* __restrict__ W1, const float* __restrict__ b1,
             const float* __restrict__ table,
             const float* __restrict__ wf, const float* __restrict__ bf,
             float* __restrict__ out,
             float* __restrict__ pd, float* __restrict__ pdT,
             float* __restrict__ tpk) {
    __shared__ __align__(16) char sb[69632];
    float* As = (float*)sb;
    float* Bs = (float*)(sb + 34816);
    int bx = blockIdx.x, tid = threadIdx.x;
    int tx = tid & 15, ty = tid >> 4;

    if (bx < 36) {
        const float* B; const float* bias; float* C; float* CT; int N, bm, bn;
        if (bx < 32) { B = Wc; bias = bc; C = out + OFF_CATGY; CT = nullptr;
                       N = 1000; bm = (bx >> 4) * 64; bn = (bx & 15) * 64; }
        else         { int t = bx - 32; B = W1; bias = b1; C = pd; CT = pdT;
                       N = 128; bm = (t >> 1) * 64; bn = (t & 1) * 64; }

#pragma unroll
        for (int p = 0; p < 8; p++) {
            int i = tid + p * 256;
            int r = i & 63, k4 = i >> 6;
            float4 v = *(const float4*)(agg + (bm + r) * 128 + k4 * 4);
            As[(k4 * 4 + 0) * 68 + r] = v.x;
            As[(k4 * 4 + 1) * 68 + r] = v.y;
            As[(k4 * 4 + 2) * 68 + r] = v.z;
            As[(k4 * 4 + 3) * 68 + r] = v.w;
        }
#pragma unroll
        for (int p = 0; p < 8; p++) {
            int i = tid + p * 256;
            int k = i >> 4, c4 = (i & 15) * 4;
            int c = bn + c4;
            float4 v = make_float4(0.f, 0.f, 0.f, 0.f);
            const float* brow = B + k * N;
            if (c + 3 < N) v = *(const float4*)(brow + c);
            else {
                if (c     < N) v.x = brow[c];
                if (c + 1 < N) v.y = brow[c + 1];
                if (c + 2 < N) v.z = brow[c + 2];
            }
            *(float4*)&Bs[k * 68 + c4] = v;
        }
        __syncthreads();

        MICRO44(As, Bs);

        int c0 = bn + tx * 4;
        float bv[4];
#pragma unroll
        for (int u = 0; u < 4; u++) bv[u] = (c0 + u < N) ? bias[c0 + u] : 0.f;
#pragma unroll
        for (int i = 0; i < 4; i++) {
            int r = bm + ty * 4 + i;
            F4U o; o.u[0] = acc[i][0]; o.u[1] = acc[i][1];
            o.s[0] += bv[0]; o.s[1] += bv[1]; o.s[2] += bv[2]; o.s[3] += bv[3];
            if (c0 + 3 < N) *(float4*)(C + r * N + c0) = o.f;
            else {
#pragma unroll
                for (int u = 0; u < 4; u++)
                    if (c0 + u < N) C[r * N + c0 + u] = o.s[u];
            }
            if (CT) {
#pragma unroll
                for (int u = 0; u < 4; u++) CT[(c0 + u) * 128 + r] = o.s[u];
            }
        }
    } else if (bx == 36) {
        float* inv  = (float*)sb;
        float* redl = (float*)sb + 128;
        if (tid < 128) {
            const float* a = agg + tid * 128;
            float s = 0.f;
#pragma unroll 8
            for (int h = 0; h < 128; h++) s = fmaf(a[h], a[h], s);
            inv[tid] = 1.f / (sqrtf(s) + 1e-12f);
        }
        __syncthreads();
        if (tid < 128) {
            float accv = 0.f;
            for (int b = 0; b < 16; b++) {
                float sv = 0.f, sq = 0.f;
#pragma unroll
                for (int d = 0; d < 8; d++) {
                    float x = agg[(b * 8 + d) * 128 + tid] * inv[b * 8 + d];
                    sv += x; sq = fmaf(x, x, sq);
                }
                accv += sv * sv - sq;
            }
            redl[tid] = accv;
        }
        __syncthreads();
        if (tid == 0) {
            float t = 0.f;
            for (int i = 0; i < 128; i++) t += redl[i];
            out[OFF_LOSS] = t / 896.f;
        }
    } else {
        // tpk GEMM: rows bm..bm+63 of table (guarded at 1000), cols bn..bn+63
        int t = bx - 37;
        int bm = (t >> 1) * 64, bn = (t & 1) * 64;
#pragma unroll
        for (int p = 0; p < 8; p++) {
            int i = tid + p * 256;
            int r = i & 63, k4 = i >> 6;
            int row = bm + r;
            float4 v = make_float4(0.f, 0.f, 0.f, 0.f);
            if (row < 1000) v = *(const float4*)(table + row * 128 + k4 * 4);
            As[(k4 * 4 + 0) * 68 + r] = v.x;
            As[(k4 * 4 + 1) * 68 + r] = v.y;
            As[(k4 * 4 + 2) * 68 + r] = v.z;
            As[(k4 * 4 + 3) * 68 + r] = v.w;
        }
#pragma unroll
        for (int p = 0; p < 8; p++) {
            int i = tid + p * 256;
            int k = i >> 4, c4 = (i & 15) * 4;
            *(float4*)&Bs[k * 68 + c4] = *(const float4*)(wf + k * 128 + bn + c4);
        }
        __syncthreads();

        MICRO44(As, Bs);

        float4 bv = *(const float4*)(bf + bn + tx * 4);
#pragma unroll
        for (int i = 0; i < 4; i++) {
            int row = bm + ty * 4 + i;
            F4U o; o.u[0] = acc[i][0]; o.u[1] = acc[i][1];
            o.s[0] += bv.x; o.s[1] += bv.y; o.s[2] += bv.z; o.s[3] += bv.w;
            *(float4*)(tpk + row * 128 + bn + tx * 4) = o.f;   // rows 1000..1023 unused
        }
    }
}

// ===========================================================================
// K3: blocks 0..255 : cand relu-GEMM (64 bd x 64 items), Q gathered from tpk;
//                     bdb==0 blocks also write emb_cand.
//     blocks 256..275: dscore via tpk gather; also write emb (40 rows/block).
// ===========================================================================
__global__ void __launch_bounds__(256, 3)
k3_scores(const float* __restrict__ pdT, const float* __restrict__ pd,
          const float* __restrict__ tpk,
          const int* __restrict__ inp, const int* __restrict__ cand,
          const float* __restrict__ table,
          const float* __restrict__ w,
          float* __restrict__ out) {
    __shared__ __align__(16) char sb[70656];
    int bx = blockIdx.x, tid = threadIdx.x;
    const float4* tp4 = (const float4*)tpk;
    const float4* t4  = (const float4*)table;

    if (bx < 256) {
        float* Ps  = (float*)sb;
        float* Qs  = (float*)(sb + 34816);
        u64*   ws2 = (u64*)(sb + 69632);
        int bdb = (bx >> 7) * 64, itb = (bx & 127) * 64;
        int tx = tid & 15, ty = tid >> 4;

#pragma unroll
        for (int p = 0; p < 8; p++) {
            int i = tid + p * 256;
            int k = i >> 4, r4 = (i & 15) * 4;
            *(float4*)&Ps[k * 68 + r4] = *(const float4*)(pdT + k * 128 + bdb + r4);
        }
#pragma unroll
        for (int p = 0; p < 8; p++) {
            int i = tid + p * 256;
            int itl = i & 63, k4 = i >> 6;
            int idx = cand[itb + itl];
            float4 v = tp4[idx * 32 + k4];
            Qs[(k4 * 4 + 0) * 68 + itl] = v.x;
            Qs[(k4 * 4 + 1) * 68 + itl] = v.y;
            Qs[(k4 * 4 + 2) * 68 + itl] = v.z;
            Qs[(k4 * 4 + 3) * 68 + itl] = v.w;
            if (bdb == 0) {
                float4 tv = t4[idx * 32 + k4];
                ((float4*)(out + OFF_ECAND + (size_t)(itb + itl) * 128))[k4] = tv;
            }
        }
        if (tid < 128) { float wv = w[tid]; ws2[tid] = pack2(wv, wv); }
        __syncthreads();

        u64 acc[4][2];
#pragma unroll
        for (int i = 0; i < 4; i++) { acc[i][0] = 0ull; acc[i][1] = 0ull; }

#pragma unroll 4
        for (int k = 0; k < 128; k++) {
            F4U a4; a4.f = *(const float4*)&Ps[k * 68 + ty * 4];
            F4U q;  q.f  = *(const float4*)&Qs[k * 68 + tx * 4];
            u64 w2 = ws2[k];
#pragma unroll
            for (int i = 0; i < 4; i++) {
                u64 ad = pack2(a4.s[i], a4.s[i]);
                acc[i][0] = fma2(relu2(add2(ad, q.u[0])), w2, acc[i][0]);
                acc[i][1] = fma2(relu2(add2(ad, q.u[1])), w2, acc[i][1]);
            }
        }

#pragma unroll
        for (int i = 0; i < 4; i++) {
            int row = bdb + ty * 4 + i;
            F4U o; o.u[0] = acc[i][0]; o.u[1] = acc[i][1];
            *(float4*)(out + OFF_DCAND + (size_t)row * NIT + itb + tx * 4) = o.f;
        }
    } else {
        int tb = bx - 256;            // 0..19
        // emb writeout: rows tb*40 .. tb*40+39
        for (int j = tid; j < 40 * 32; j += 256) {
            int row = tb * 40 + (j >> 5);
            int k4 = j & 31;
            int idx = inp[row];
            ((float4*)(out + OFF_EMB + row * 128))[k4] = t4[idx * 32 + k4];
        }

        int wid0 = tb * 8 + (tid >> 5);
        int lane = tid & 31;
        const float4* w4 = (const float4*)w;
        float4 ww = w4[lane];
#pragma unroll
        for (int rep = 0; rep < 5; rep++) {
            int wid = wid0 + rep * 160;
            if (wid >= 800) break;
            int b = wid / 50, l = wid % 50;
            int idx = inp[b * 50 + l];
            float4 c = tp4[idx * 32 + lane];
#pragma unroll
            for (int d = 0; d < 8; d++) {
                const float4* p4 = (const float4*)(pd + (b * 8 + d) * 128);
                float4 a = p4[lane];
                float acc = fmaxf(a.x + c.x, 0.f) * ww.x
                          + fmaxf(a.y + c.y, 0.f) * ww.y
                          + fmaxf(a.z + c.z, 0.f) * ww.z
                          + fmaxf(a.w + c.w, 0.f) * ww.w;
#pragma unroll
                for (int o = 16; o > 0; o >>= 1) acc += __shfl_down_sync(0xffffffffu, acc, o);
                if (lane == 0) out[OFF_DSC + b * 400 + l * 8 + d] = acc;
            }
        }
    }
}

// ===========================================================================
extern "C" void kernel_launch(void* const* d_in, const int* in_sizes, int n_in,
                              void* d_out, int out_size) {
    const int*   input = (const int*)d_in[0];
    const int*   cand  = (const int*)d_in[1];
    const float* table = (const float*)d_in[4];
    const float* Wd    = (const float*)d_in[5];
    const float* Wk    = (const float*)d_in[6];
    const float* bk    = (const float*)d_in[7];
    const float* W1    = (const float*)d_in[8];
    const float* b1    = (const float*)d_in[9];
    const float* wsc   = (const float*)d_in[10];
    const float* Wc    = (const float*)d_in[11];
    const float* bc    = (const float*)d_in[12];
    float* out = (float*)d_out;

    float *wf, *bf, *agg, *pd, *pdT, *tpk;
    cudaGetSymbolAddress((void**)&wf,  g_wf);
    cudaGetSymbolAddress((void**)&bf,  g_bf);
    cudaGetSymbolAddress((void**)&agg, g_agg);
    cudaGetSymbolAddress((void**)&pd,  g_pd);
    cudaGetSymbolAddress((void**)&pdT, g_pdT);
    cudaGetSymbolAddress((void**)&tpk, g_tpk);

    const float* Wk1 = W1 + 128 * 128;

    k1_lse_fold <<<261, 256>>>(input, table, Wd, Wk, Wk1, bk, agg, wf, bf);
    k2_heads_tpk<<<69, 256>>>(agg, Wc, bc, W1, b1, table, wf, bf, out, pd, pdT, tpk);
    k3_scores   <<<276, 256>>>(pdT, pd, tpk, input, cand, table, wsc, out);
}